// round 7
// baseline (speedup 1.0000x reference)
#include <cuda_runtime.h>
#include <cuda_bf16.h>
#include <math.h>
#include <string.h>

// support [25,2560] f32, query [4096,2560] f32 -> out [4096,5] f32
#define D       2560
#define NS      25
#define NSB     26              // 25 supports + 1 ones-row (gives qsum)
#define NPAD    32
#define NQ      4096
#define NWAY    5
#define KSHOT   5
#define EPSV    1e-6f

#define NSPLIT  8
#define DQ      320             // K per CTA
#define NCHUNK  20              // DQ / 16
#define MROWS   128             // query rows per CTA
#define NRB     32              // NQ / MROWS
#define THREADS 256
#define BSTRIDE 328             // bf16 elems per B smem row (conflict-free)
#define PF      4               // A-fragment prefetch depth (chunks)

typedef unsigned long long u64;

__device__ float g_dot[NSPLIT][NRB][NSB][MROWS];
__device__ float g_qn [NSPLIT][NRB][MROWS];
__device__ float g_sn [NSPLIT][NS];
__device__ int   g_ctr[NRB];    // zero-init; self-resetting per launch

__device__ __forceinline__ u64 ffma2(u64 a, u64 b, u64 c) {
    u64 d;
    asm("fma.rn.f32x2 %0, %1, %2, %3;" : "=l"(d) : "l"(a), "l"(b), "l"(c));
    return d;
}
__device__ __forceinline__ float f2_sum(u64 v) {
    return __uint_as_float((unsigned)(v & 0xffffffffull)) +
           __uint_as_float((unsigned)(v >> 32));
}
__device__ __forceinline__ u64 as_u64(float2 v) {
    u64 r; memcpy(&r, &v, 8); return r;
}
__device__ __forceinline__ unsigned cvt_bf2(float2 v) {
    __nv_bfloat162 p = __floats2bfloat162_rn(v.x, v.y);
    unsigned r; memcpy(&r, &p, 4); return r;
}

__device__ __forceinline__ void mma16816(float c[4],
                                         unsigned a0, unsigned a1,
                                         unsigned a2, unsigned a3,
                                         unsigned b0, unsigned b1) {
    asm volatile(
        "mma.sync.aligned.m16n8k16.row.col.f32.bf16.bf16.f32 "
        "{%0,%1,%2,%3}, {%4,%5,%6,%7}, {%8,%9}, {%0,%1,%2,%3};"
        : "+f"(c[0]), "+f"(c[1]), "+f"(c[2]), "+f"(c[3])
        : "r"(a0), "r"(a1), "r"(a2), "r"(a3), "r"(b0), "r"(b1));
}

// ---------------------------------------------------------------------------
// CTA = (row block rb, K-eighth qd). 2 CTAs/SM. 8 warps, warp owns 16 rows.
// B (support bf16) staged once in smem; row 25 = ones (dot -> qsum).
// A fragments streamed from global through a 4-deep register prefetch
// pipeline (keeps ~16 independent 32B loads in flight per warp).
// ---------------------------------------------------------------------------
__global__ __launch_bounds__(THREADS, 2)
void pd_mma(const float* __restrict__ support,
            const float* __restrict__ query,
            float* __restrict__ out) {
    __shared__ __align__(16) __nv_bfloat16 Bs[NPAD][BSTRIDE];
    __shared__ float s_red[NS][8][2];
    __shared__ float s_sn[NS];
    __shared__ int   s_flag;

    const int tid  = threadIdx.x;
    const int warp = tid >> 5;
    const int ln   = tid & 31;
    const int gid  = ln >> 2;        // quad row / n index
    const int tig  = ln & 3;         // position in quad
    const int rb   = blockIdx.x;
    const int qd   = blockIdx.y;
    const int dstart = qd * DQ;

    // ---- ones row (25) and zero pad rows (26..31) ----
    for (int i = tid; i < (NPAD - NS) * BSTRIDE; i += THREADS) {
        const int r = NS + i / BSTRIDE;
        const int c = i % BSTRIDE;
        Bs[r][c] = __float2bfloat16(r == NS ? 1.f : 0.f);
    }

    // ---- stage B: 25x320 f32 -> bf16 (rounded), plus ssq/ssm partials ----
    if (tid < NS * 8) {
        const int n  = tid >> 3;
        const int kc = tid & 7;                    // 40-col strip
        const float* src = support + (size_t)n * D + dstart + kc * 40;
        float ssq = 0.f, ssm = 0.f;
        #pragma unroll
        for (int j = 0; j < 10; ++j) {
            const float4 v = *reinterpret_cast<const float4*>(src + j * 4);
            const __nv_bfloat162 p0 = __floats2bfloat162_rn(v.x, v.y);
            const __nv_bfloat162 p1 = __floats2bfloat162_rn(v.z, v.w);
            const float r0 = __bfloat162float(p0.x), r1 = __bfloat162float(p0.y);
            const float r2 = __bfloat162float(p1.x), r3 = __bfloat162float(p1.y);
            ssq = fmaf(r0, r0, ssq); ssq = fmaf(r1, r1, ssq);
            ssq = fmaf(r2, r2, ssq); ssq = fmaf(r3, r3, ssq);
            ssm += (r0 + r1) + (r2 + r3);
            u64 u; memcpy(&u, &p0, 4); memcpy(((char*)&u) + 4, &p1, 4);
            *reinterpret_cast<u64*>(&Bs[n][kc * 40 + j * 4]) = u;
        }
        s_red[n][kc][0] = ssq;
        s_red[n][kc][1] = ssm;
    }
    __syncthreads();
    if (tid < NS) {
        float a = 0.f, b = 0.f;
        #pragma unroll
        for (int o = 0; o < 8; ++o) { a += s_red[tid][o][0]; b += s_red[tid][o][1]; }
        g_sn[qd][tid] = a + 2.f * EPSV * b;   // ||s~||^2 + 2 eps sum(s~) (eighth)
    }

    // ---- mainloop: 20 k-chunks of 16, 4 n-tiles of 8, PF=4 prefetch ----
    const int lrow = warp * 16 + gid;
    const float* qa = query + (size_t)(rb * MROWS + lrow) * D + dstart + tig * 2;
    const float* qb = qa + (size_t)8 * D;

    float c[4][4];
    #pragma unroll
    for (int nt = 0; nt < 4; ++nt)
        #pragma unroll
        for (int i = 0; i < 4; ++i) c[nt][i] = 0.f;
    u64 qn0 = 0ull, qn1 = 0ull;

    const __nv_bfloat16* brow = &Bs[gid][tig * 2];

    float2 pa[PF][4];
    #pragma unroll
    for (int p = 0; p < PF; ++p) {
        const int k0 = p * 16;
        pa[p][0] = *reinterpret_cast<const float2*>(qa + k0);
        pa[p][1] = *reinterpret_cast<const float2*>(qb + k0);
        pa[p][2] = *reinterpret_cast<const float2*>(qa + k0 + 8);
        pa[p][3] = *reinterpret_cast<const float2*>(qb + k0 + 8);
    }

    #pragma unroll
    for (int ch = 0; ch < NCHUNK; ++ch) {
        const int slot = ch & (PF - 1);
        const float2 a0 = pa[slot][0];
        const float2 a1 = pa[slot][1];
        const float2 a2 = pa[slot][2];
        const float2 a3 = pa[slot][3];
        if (ch + PF < NCHUNK) {
            const int k0 = (ch + PF) * 16;
            pa[slot][0] = *reinterpret_cast<const float2*>(qa + k0);
            pa[slot][1] = *reinterpret_cast<const float2*>(qb + k0);
            pa[slot][2] = *reinterpret_cast<const float2*>(qa + k0 + 8);
            pa[slot][3] = *reinterpret_cast<const float2*>(qb + k0 + 8);
        }
        qn0 = ffma2(as_u64(a0), as_u64(a0), qn0);
        qn0 = ffma2(as_u64(a2), as_u64(a2), qn0);
        qn1 = ffma2(as_u64(a1), as_u64(a1), qn1);
        qn1 = ffma2(as_u64(a3), as_u64(a3), qn1);
        const unsigned ra0 = cvt_bf2(a0);
        const unsigned ra1 = cvt_bf2(a1);
        const unsigned ra2 = cvt_bf2(a2);
        const unsigned ra3 = cvt_bf2(a3);
        const int k0 = ch * 16;
        #pragma unroll
        for (int nt = 0; nt < 4; ++nt) {
            const __nv_bfloat16* bp = brow + nt * 8 * BSTRIDE + k0;
            const unsigned b0 = *reinterpret_cast<const unsigned*>(bp);
            const unsigned b1 = *reinterpret_cast<const unsigned*>(bp + 8);
            mma16816(c[nt], ra0, ra1, ra2, ra3, b0, b1);
        }
    }

    // ---- qn: reduce over the 4 quad lanes (same row) ----
    float q0 = f2_sum(qn0), q1 = f2_sum(qn1);
    q0 += __shfl_xor_sync(0xffffffffu, q0, 1);
    q0 += __shfl_xor_sync(0xffffffffu, q0, 2);
    q1 += __shfl_xor_sync(0xffffffffu, q1, 1);
    q1 += __shfl_xor_sync(0xffffffffu, q1, 2);
    if (tig == 0) {
        g_qn[qd][rb][lrow]     = q0;
        g_qn[qd][rb][lrow + 8] = q1;
    }

    // ---- publish dot partials ----
    #pragma unroll
    for (int nt = 0; nt < 4; ++nt) {
        const int s = nt * 8 + tig * 2;
        if (s < NSB) {
            g_dot[qd][rb][s][lrow]     = c[nt][0];
            g_dot[qd][rb][s][lrow + 8] = c[nt][2];
        }
        if (s + 1 < NSB) {
            g_dot[qd][rb][s + 1][lrow]     = c[nt][1];
            g_dot[qd][rb][s + 1][lrow + 8] = c[nt][3];
        }
    }

    __threadfence();
    __syncthreads();
    if (tid == 0) s_flag = atomicAdd(&g_ctr[rb], 1);
    __syncthreads();

    // ---- last CTA of this row block finishes ----
    if (s_flag == NSPLIT - 1) {
        if (tid < NS) {
            float a = 0.f;
            #pragma unroll
            for (int q = 0; q < NSPLIT; ++q) a += g_sn[q][tid];
            s_sn[tid] = a;
        }
        __syncthreads();
        if (tid < MROWS) {
            const int r = tid;
            float dt[NS];
            #pragma unroll
            for (int s = 0; s < NS; ++s) dt[s] = 0.f;
            float qnT = 0.f, qsT = 0.f;
            #pragma unroll
            for (int q = 0; q < NSPLIT; ++q) {
                #pragma unroll
                for (int s = 0; s < NS; ++s) dt[s] += g_dot[q][rb][s][r];
                qsT += g_dot[q][rb][25][r];     // ones-row dot = sum(q~)
                qnT += g_qn[q][rb][r];
            }
            // d2 = qn + (ssq + 2 eps ssm) + D eps^2 - 2 dot - 2 eps qsum
            const float base = qnT - 2.f * EPSV * qsT + (float)D * (EPSV * EPSV);
            #pragma unroll
            for (int w = 0; w < NWAY; ++w) {
                float sum = 0.f;
                #pragma unroll
                for (int k = 0; k < KSHOT; ++k) {
                    const int s = w * KSHOT + k;
                    const float d2 = base + s_sn[s] - 2.f * dt[s];
                    sum += sqrtf(fmaxf(d2, 0.f));
                }
                out[(size_t)(rb * MROWS + r) * NWAY + w] = -sum;
            }
        }
        if (tid == 0) g_ctr[rb] = 0;   // reset for next replay
    }
}

// ---------------------------------------------------------------------------
extern "C" void kernel_launch(void* const* d_in, const int* in_sizes, int n_in,
                              void* d_out, int out_size) {
    const float* support = (const float*)d_in[0];
    const float* query   = (const float*)d_in[1];
    if (n_in >= 2 && in_sizes[0] > in_sizes[1]) {
        const float* t = support; support = query; query = t;
    }
    float* out = (float*)d_out;

    pd_mma<<<dim3(NRB, NSPLIT), THREADS>>>(support, query, out);
}